// round 1
// baseline (speedup 1.0000x reference)
#include <cuda_runtime.h>

#define NUM_LEVELS 16
#define TOTAL_PARAMS 7131240

// Scratch: table accumulator/result and per-vertex counts (static device arrays; no allocs).
__device__ float g_table[TOTAL_PARAMS * 2];
__device__ float g_counts[TOTAL_PARAMS];

__constant__ int c_offsets[NUM_LEVELS] = {
    0, 4920, 40864, 315496, 839784, 1364072, 1888360, 2412648,
    2936936, 3461224, 3985512, 4509800, 5034088, 5558376, 6082664, 6606952
};

// ---------------------------------------------------------------------------
// 1) zero the accumulators (graph-replay safe: re-zeroed every call)
// ---------------------------------------------------------------------------
__global__ __launch_bounds__(256) void zero_kernel() {
    int i = blockIdx.x * blockDim.x + threadIdx.x;
    float4 z = make_float4(0.f, 0.f, 0.f, 0.f);
    if (i < (TOTAL_PARAMS * 2) / 4) reinterpret_cast<float4*>(g_table)[i] = z;
    if (i < TOTAL_PARAMS / 4)       reinterpret_cast<float4*>(g_counts)[i] = z;
}

// ---------------------------------------------------------------------------
// 2) scatter-add point embeddings + counts
// ---------------------------------------------------------------------------
__global__ __launch_bounds__(256) void scatter_kernel(
    const float2* __restrict__ emb, const int* __restrict__ sidx, int n)
{
    int i = blockIdx.x * blockDim.x + threadIdx.x;
    if (i >= n) return;
    int idx = sidx[i];
    float2 e = emb[i];
    atomicAdd(&g_table[idx * 2 + 0], e.x);
    atomicAdd(&g_table[idx * 2 + 1], e.y);
    atomicAdd(&g_counts[idx], 1.0f);
}

// ---------------------------------------------------------------------------
// 3) blend: table[i] = count>0 ? sum/count : fs[i]
//    (matches (sum/max(c,1))*min(c,1) + fs*(1-min(c,1)) exactly)
// ---------------------------------------------------------------------------
__global__ __launch_bounds__(256) void blend_kernel(const float2* __restrict__ fs) {
    int i = blockIdx.x * blockDim.x + threadIdx.x;
    if (i >= TOTAL_PARAMS) return;
    float c = g_counts[i];
    float2* tp = reinterpret_cast<float2*>(g_table);
    float2 s = tp[i];
    if (c > 0.f) {
        s.x = s.x / c;
        s.y = s.y / c;
    } else {
        s = __ldg(&fs[i]);
    }
    tp[i] = s;
}

// ---------------------------------------------------------------------------
// 4) grid encode: one thread per (point, level)
// ---------------------------------------------------------------------------
__global__ __launch_bounds__(256) void encode_kernel(
    const float* __restrict__ xin, const int* __restrict__ boundp,
    float* __restrict__ out, int B)
{
    int t = blockIdx.x * blockDim.x + threadIdx.x;
    if (t >= B * NUM_LEVELS) return;
    int b = t >> 4;
    int level = t & 15;

    // bound is a scalar input; hedge on dtype (int32 expected, value 1).
    float bound = 1.0f;
    if (boundp) {
        int iv = *boundp;
        if (iv >= 1 && iv <= 1000000) bound = (float)iv;
        else bound = __int_as_float(iv);
    }
    float denom = 2.0f * bound;

    float x = (xin[b * 3 + 0] + bound) / denom;
    float y = (xin[b * 3 + 1] + bound) / denom;
    float z = (xin[b * 3 + 2] + bound) / denom;

    int res = 16 << level;
    float scale = (float)res - 1.0f;

    // pos = x*scale + 0.5 with explicit mul+add (no fma) to match reference floor boundaries
    float px = __fadd_rn(__fmul_rn(x, scale), 0.5f);
    float py = __fadd_rn(__fmul_rn(y, scale), 0.5f);
    float pz = __fadd_rn(__fmul_rn(z, scale), 0.5f);

    float fxf = floorf(px), fyf = floorf(py), fzf = floorf(pz);
    float rx = px - fxf, ry = py - fyf, rz = pz - fzf;
    int gx = (int)fxf, gy = (int)fyf, gz = (int)fzf;

    float wx[2] = {1.0f - rx, rx};
    float wy[2] = {1.0f - ry, ry};
    float wz[2] = {1.0f - rz, rz};

    const float2* tab = reinterpret_cast<const float2*>(g_table) + c_offsets[level];
    float o0 = 0.f, o1 = 0.f;

    if (level < 3) {
        // dense level: row-major; max index < padded hashmap size, modulo is a no-op
        int r1 = res + 1;
        int base = gx + gy * r1 + gz * r1 * r1;
        #pragma unroll
        for (int c = 0; c < 8; c++) {
            int bx = c & 1, by = (c >> 1) & 1, bz = c >> 2;
            int idx = base + bx + by * r1 + bz * (r1 * r1);
            float2 v = __ldg(tab + idx);
            float w = wx[bx] * wy[by] * wz[bz];
            o0 = fmaf(w, v.x, o0);
            o1 = fmaf(w, v.y, o1);
        }
    } else {
        // hashed level: all hashed sizes are 2^19 -> mask
        unsigned hx0 = (unsigned)gx;
        unsigned hx1 = hx0 + 1u;
        unsigned hy0 = (unsigned)gy * 2654435761u;
        unsigned hy1 = (unsigned)(gy + 1) * 2654435761u;
        unsigned hz0 = (unsigned)gz * 805459861u;
        unsigned hz1 = (unsigned)(gz + 1) * 805459861u;
        const unsigned mask = (1u << 19) - 1u;
        #pragma unroll
        for (int c = 0; c < 8; c++) {
            int bx = c & 1, by = (c >> 1) & 1, bz = c >> 2;
            unsigned idx = ((bx ? hx1 : hx0) ^ (by ? hy1 : hy0) ^ (bz ? hz1 : hz0)) & mask;
            float2 v = __ldg(tab + idx);
            float w = wx[bx] * wy[by] * wz[bz];
            o0 = fmaf(w, v.x, o0);
            o1 = fmaf(w, v.y, o1);
        }
    }

    float2 r;
    r.x = o0;
    r.y = o1;
    reinterpret_cast<float2*>(out)[(long)b * NUM_LEVELS + level] = r;
}

// ---------------------------------------------------------------------------
extern "C" void kernel_launch(void* const* d_in, const int* in_sizes, int n_in,
                              void* d_out, int out_size)
{
    const float*  inputs = (const float*)d_in[0];
    const float2* emb    = (const float2*)d_in[1];
    const float2* fs     = (const float2*)d_in[2];
    const int*    sidx   = (const int*)d_in[3];
    const int*    boundp = (n_in > 4) ? (const int*)d_in[4] : nullptr;

    int B = in_sizes[0] / 3;
    int N = in_sizes[3];

    int zthreads = (TOTAL_PARAMS * 2) / 4;  // covers both arrays (table half-count is larger)
    zero_kernel<<<(zthreads + 255) / 256, 256>>>();
    scatter_kernel<<<(N + 255) / 256, 256>>>(emb, sidx, N);
    blend_kernel<<<(TOTAL_PARAMS + 255) / 256, 256>>>(fs);
    encode_kernel<<<(B * NUM_LEVELS + 255) / 256, 256>>>(inputs, boundp, (float*)d_out, B);
}

// round 4
// speedup vs baseline: 1.0330x; 1.0330x over previous
#include <cuda_runtime.h>

#define NUM_LEVELS 16
#define TOTAL_PARAMS 7131240

// Scratch: table accumulator/result and per-vertex counts (static device arrays; no allocs).
__device__ __align__(16) float g_table[TOTAL_PARAMS * 2];
__device__ __align__(16) float g_counts[TOTAL_PARAMS];

__constant__ int c_offsets[NUM_LEVELS] = {
    0, 4920, 40864, 315496, 839784, 1364072, 1888360, 2412648,
    2936936, 3461224, 3985512, 4509800, 5034088, 5558376, 6082664, 6606952
};

// ---------------------------------------------------------------------------
// 1) zero the accumulators (graph-replay safe: re-zeroed every call)
// ---------------------------------------------------------------------------
__global__ __launch_bounds__(256) void zero_kernel() {
    int i = blockIdx.x * blockDim.x + threadIdx.x;
    float4 z = make_float4(0.f, 0.f, 0.f, 0.f);
    if (i < (TOTAL_PARAMS * 2) / 4) reinterpret_cast<float4*>(g_table)[i] = z;
    if (i < TOTAL_PARAMS / 4)       reinterpret_cast<float4*>(g_counts)[i] = z;
}

// ---------------------------------------------------------------------------
// 2) scatter-add point embeddings + counts (vector atomic for the sum)
// ---------------------------------------------------------------------------
__global__ __launch_bounds__(256) void scatter_kernel(
    const float2* __restrict__ emb, const int* __restrict__ sidx, int n)
{
    int i = blockIdx.x * blockDim.x + threadIdx.x;
    if (i >= n) return;
    int idx = sidx[i];
    float2 e = emb[i];
#if __CUDA_ARCH__ >= 900
    atomicAdd(reinterpret_cast<float2*>(&g_table[idx * 2]), e);
#else
    atomicAdd(&g_table[idx * 2 + 0], e.x);
    atomicAdd(&g_table[idx * 2 + 1], e.y);
#endif
    atomicAdd(&g_counts[idx], 1.0f);
}

// ---------------------------------------------------------------------------
// 3) blend: table[i] = count>0 ? sum/count : fs[i]
//    (matches (sum/max(c,1))*min(c,1) + fs*(1-min(c,1)) exactly)
// ---------------------------------------------------------------------------
__global__ __launch_bounds__(256) void blend_kernel(const float2* __restrict__ fs) {
    int i = blockIdx.x * blockDim.x + threadIdx.x;
    if (i >= TOTAL_PARAMS) return;
    float c = g_counts[i];
    float2* tp = reinterpret_cast<float2*>(g_table);
    float2 s = tp[i];
    if (c > 0.f) {
        s.x = s.x / c;
        s.y = s.y / c;
    } else {
        s = __ldg(&fs[i]);
    }
    tp[i] = s;
}

// ---------------------------------------------------------------------------
// 4) grid encode: one thread per (point, level), paired corner loads
// ---------------------------------------------------------------------------
__global__ __launch_bounds__(256) void encode_kernel(
    const float* __restrict__ xin, const int* __restrict__ boundp,
    float* __restrict__ out, int B)
{
    int t = blockIdx.x * blockDim.x + threadIdx.x;
    if (t >= B * NUM_LEVELS) return;
    int b = t >> 4;
    int level = t & 15;

    // bound is a scalar input; hedge on dtype (int32 expected, value 1).
    float bound = 1.0f;
    if (boundp) {
        int iv = *boundp;
        if (iv >= 1 && iv <= 1000000) bound = (float)iv;
        else bound = __int_as_float(iv);
    }
    float denom = 2.0f * bound;

    float x = (xin[b * 3 + 0] + bound) / denom;
    float y = (xin[b * 3 + 1] + bound) / denom;
    float z = (xin[b * 3 + 2] + bound) / denom;

    int res = 16 << level;
    float scale = (float)res - 1.0f;

    // pos = x*scale + 0.5 with explicit mul+add (no fma) to match reference floor boundaries
    float px = __fadd_rn(__fmul_rn(x, scale), 0.5f);
    float py = __fadd_rn(__fmul_rn(y, scale), 0.5f);
    float pz = __fadd_rn(__fmul_rn(z, scale), 0.5f);

    float fxf = floorf(px), fyf = floorf(py), fzf = floorf(pz);
    float rx = px - fxf, ry = py - fyf, rz = pz - fzf;
    int gx = (int)fxf, gy = (int)fyf, gz = (int)fzf;

    float wx0 = 1.0f - rx, wx1 = rx;
    float wy[2] = {1.0f - ry, ry};
    float wz[2] = {1.0f - rz, rz};

    const float2* tab = reinterpret_cast<const float2*>(g_table) + c_offsets[level];
    float o0 = 0.f, o1 = 0.f;

    if (level < 3) {
        // dense level: row-major; max dense index < padded hashmap size (no modulo)
        int r1 = res + 1;
        int base = gx + gy * r1 + gz * r1 * r1;
        #pragma unroll
        for (int c2 = 0; c2 < 4; c2++) {
            int by = c2 & 1, bz = c2 >> 1;
            int i0 = base + by * r1 + bz * (r1 * r1);
            float wyz = wy[by] * wz[bz];
            float2 v0, v1;
            if ((i0 & 1) == 0) {
                float4 v = __ldg(reinterpret_cast<const float4*>(tab + i0));
                v0 = make_float2(v.x, v.y);
                v1 = make_float2(v.z, v.w);
            } else {
                v0 = __ldg(tab + i0);
                v1 = __ldg(tab + i0 + 1);
            }
            float w0 = wyz * wx0, w1 = wyz * wx1;
            o0 = fmaf(w0, v0.x, o0); o1 = fmaf(w0, v0.y, o1);
            o0 = fmaf(w1, v1.x, o0); o1 = fmaf(w1, v1.y, o1);
        }
    } else {
        // hashed level: all hashed sizes are 2^19 -> mask
        const unsigned mask = (1u << 19) - 1u;
        unsigned hx0 = (unsigned)gx;
        unsigned hx1 = hx0 + 1u;
        unsigned hy0 = (unsigned)gy * 2654435761u;
        unsigned hy1 = (unsigned)(gy + 1) * 2654435761u;
        unsigned hz0 = (unsigned)gz * 805459861u;
        unsigned hz1 = (unsigned)(gz + 1) * 805459861u;
        unsigned dx = (hx0 ^ hx1) & mask;   // == 1 iff gx even (50% of lanes)
        bool paired = (dx == 1u);
        #pragma unroll
        for (int c2 = 0; c2 < 4; c2++) {
            int by = c2 & 1, bz = c2 >> 1;
            unsigned hyz = (by ? hy1 : hy0) ^ (bz ? hz1 : hz0);
            unsigned i0 = (hx0 ^ hyz) & mask;
            float wyz = wy[by] * wz[bz];
            float2 v0, v1;
            if (paired) {
                // corners at i0 and i0^1: two halves of one aligned float4
                unsigned lo = i0 & ~1u;
                float4 v = __ldg(reinterpret_cast<const float4*>(tab + lo));
                if (i0 & 1) {
                    v0 = make_float2(v.z, v.w);
                    v1 = make_float2(v.x, v.y);
                } else {
                    v0 = make_float2(v.x, v.y);
                    v1 = make_float2(v.z, v.w);
                }
            } else {
                unsigned i1 = i0 ^ dx;
                v0 = __ldg(tab + i0);
                v1 = __ldg(tab + i1);
            }
            float w0 = wyz * wx0, w1 = wyz * wx1;
            o0 = fmaf(w0, v0.x, o0); o1 = fmaf(w0, v0.y, o1);
            o0 = fmaf(w1, v1.x, o0); o1 = fmaf(w1, v1.y, o1);
        }
    }

    float2 r;
    r.x = o0;
    r.y = o1;
    reinterpret_cast<float2*>(out)[(long)b * NUM_LEVELS + level] = r;
}

// ---------------------------------------------------------------------------
extern "C" void kernel_launch(void* const* d_in, const int* in_sizes, int n_in,
                              void* d_out, int out_size)
{
    const float*  inputs = (const float*)d_in[0];
    const float2* emb    = (const float2*)d_in[1];
    const float2* fs     = (const float2*)d_in[2];
    const int*    sidx   = (const int*)d_in[3];
    const int*    boundp = (n_in > 4) ? (const int*)d_in[4] : nullptr;

    int B = in_sizes[0] / 3;
    int N = in_sizes[3];

    int zthreads = (TOTAL_PARAMS * 2) / 4;  // covers both arrays (table half-count is larger)
    zero_kernel<<<(zthreads + 255) / 256, 256>>>();
    scatter_kernel<<<(N + 255) / 256, 256>>>(emb, sidx, N);
    blend_kernel<<<(TOTAL_PARAMS + 255) / 256, 256>>>(fs);
    encode_kernel<<<(B * NUM_LEVELS + 255) / 256, 256>>>(inputs, boundp, (float*)d_out, B);
}

// round 7
// speedup vs baseline: 1.0568x; 1.0230x over previous
#include <cuda_runtime.h>

#define NUM_LEVELS 16
#define TOTAL_PARAMS 7131240

// Accumulator: (sum.x, sum.y, count, pad) per vertex. Zero-initialized (.bss) on
// load; blend_kernel re-zeroes it after consuming, so every graph replay starts
// from a clean accumulator without a dedicated zero pass.
__device__ __align__(16) float4 g_acc[TOTAL_PARAMS];
// Final blended table consumed by encode.
__device__ __align__(16) float g_table[TOTAL_PARAMS * 2];

__constant__ int c_offsets[NUM_LEVELS] = {
    0, 4920, 40864, 315496, 839784, 1364072, 1888360, 2412648,
    2936936, 3461224, 3985512, 4509800, 5034088, 5558376, 6082664, 6606952
};

// ---------------------------------------------------------------------------
// 1) scatter-add point embeddings + counts: one 16B vector atomic per point
// ---------------------------------------------------------------------------
__global__ __launch_bounds__(256) void scatter_kernel(
    const float2* __restrict__ emb, const int* __restrict__ sidx, int n)
{
    int i = blockIdx.x * blockDim.x + threadIdx.x;
    if (i >= n) return;
    int idx = sidx[i];
    float2 e = emb[i];
#if __CUDA_ARCH__ >= 900
    atomicAdd(&g_acc[idx], make_float4(e.x, e.y, 1.0f, 0.0f));
#else
    atomicAdd(&g_acc[idx].x, e.x);
    atomicAdd(&g_acc[idx].y, e.y);
    atomicAdd(&g_acc[idx].z, 1.0f);
#endif
}

// ---------------------------------------------------------------------------
// 2) blend: table[i] = count>0 ? sum/count : fs[i]; then re-zero accumulator.
//    Two vertices per thread, all 16B transactions.
// ---------------------------------------------------------------------------
__global__ __launch_bounds__(256) void blend_kernel(const float4* __restrict__ fs4) {
    int i2 = blockIdx.x * blockDim.x + threadIdx.x;   // pair index
    if (i2 >= TOTAL_PARAMS / 2) return;
    int i = i2 * 2;
    float4 a0 = g_acc[i];
    float4 a1 = g_acc[i + 1];
    float4 f  = __ldg(&fs4[i2]);                      // fs for vertices i, i+1
    float4 r;
    if (a0.z > 0.f) { r.x = a0.x / a0.z; r.y = a0.y / a0.z; }
    else            { r.x = f.x;         r.y = f.y; }
    if (a1.z > 0.f) { r.z = a1.x / a1.z; r.w = a1.y / a1.z; }
    else            { r.z = f.z;         r.w = f.w; }
    reinterpret_cast<float4*>(g_table)[i2] = r;
    float4 zero = make_float4(0.f, 0.f, 0.f, 0.f);
    g_acc[i]     = zero;
    g_acc[i + 1] = zero;
}

// ---------------------------------------------------------------------------
// 3) grid encode: one thread per (point, level).
//    Branchless paired loads: the aligned float4 at (i0 & ~1) always contains
//    corner i0; the second corner needs an extra (predicated) load only when
//    i1 != (i0 ^ 1).
// ---------------------------------------------------------------------------
__global__ __launch_bounds__(256) void encode_kernel(
    const float* __restrict__ xin, const int* __restrict__ boundp,
    float* __restrict__ out, int B)
{
    int t = blockIdx.x * blockDim.x + threadIdx.x;
    if (t >= B * NUM_LEVELS) return;
    int b = t >> 4;
    int level = t & 15;

    // bound is a scalar input; hedge on dtype (int32 expected, value 1).
    float bound = 1.0f;
    if (boundp) {
        int iv = *boundp;
        if (iv >= 1 && iv <= 1000000) bound = (float)iv;
        else bound = __int_as_float(iv);
    }
    float denom = 2.0f * bound;

    float x = (xin[b * 3 + 0] + bound) / denom;
    float y = (xin[b * 3 + 1] + bound) / denom;
    float z = (xin[b * 3 + 2] + bound) / denom;

    int res = 16 << level;
    float scale = (float)res - 1.0f;

    // pos = x*scale + 0.5 with explicit mul+add (no fma) to match reference
    float px = __fadd_rn(__fmul_rn(x, scale), 0.5f);
    float py = __fadd_rn(__fmul_rn(y, scale), 0.5f);
    float pz = __fadd_rn(__fmul_rn(z, scale), 0.5f);

    float fxf = floorf(px), fyf = floorf(py), fzf = floorf(pz);
    float rx = px - fxf, ry = py - fyf, rz = pz - fzf;
    int gx = (int)fxf, gy = (int)fyf, gz = (int)fzf;

    float wx0 = 1.0f - rx, wx1 = rx;
    float wy[2] = {1.0f - ry, ry};
    float wz[2] = {1.0f - rz, rz};

    const float2* tab = reinterpret_cast<const float2*>(g_table) + c_offsets[level];

    // --- index computation for the 4 (by,bz) corner pairs -------------------
    unsigned i0[4], i1[4];
    if (level < 3) {
        // dense level: row-major; max dense index < padded hashmap size
        int r1 = res + 1;
        int base = gx + gy * r1 + gz * r1 * r1;
        #pragma unroll
        for (int c2 = 0; c2 < 4; c2++) {
            int by = c2 & 1, bz = c2 >> 1;
            i0[c2] = (unsigned)(base + by * r1 + bz * (r1 * r1));
            i1[c2] = i0[c2] + 1u;
        }
    } else {
        // hashed level: all hashed sizes are 2^19 -> mask
        const unsigned mask = (1u << 19) - 1u;
        unsigned hx0 = (unsigned)gx;
        unsigned hx1 = hx0 + 1u;
        unsigned hy0 = (unsigned)gy * 2654435761u;
        unsigned hy1 = (unsigned)(gy + 1) * 2654435761u;
        unsigned hz0 = (unsigned)gz * 805459861u;
        unsigned hz1 = (unsigned)(gz + 1) * 805459861u;
        #pragma unroll
        for (int c2 = 0; c2 < 4; c2++) {
            int by = c2 & 1, bz = c2 >> 1;
            unsigned hyz = (by ? hy1 : hy0) ^ (bz ? hz1 : hz0);
            i0[c2] = (hx0 ^ hyz) & mask;
            i1[c2] = (hx1 ^ hyz) & mask;
        }
    }

    // --- batched loads (maximize MLP) ---------------------------------------
    float4 q[4];
    float2 e[4];
    #pragma unroll
    for (int c2 = 0; c2 < 4; c2++) {
        q[c2] = __ldg(reinterpret_cast<const float4*>(tab + (i0[c2] & ~1u)));
        bool paired = (i1[c2] == (i0[c2] ^ 1u));
        e[c2] = make_float2(0.f, 0.f);
        if (!paired) e[c2] = __ldg(tab + i1[c2]);
    }

    // --- combine -------------------------------------------------------------
    float o0 = 0.f, o1 = 0.f;
    #pragma unroll
    for (int c2 = 0; c2 < 4; c2++) {
        int by = c2 & 1, bz = c2 >> 1;
        float wyz = wy[by] * wz[bz];
        bool hi = (i0[c2] & 1u) != 0u;
        bool paired = (i1[c2] == (i0[c2] ^ 1u));
        float2 v0 = hi ? make_float2(q[c2].z, q[c2].w) : make_float2(q[c2].x, q[c2].y);
        float2 other = hi ? make_float2(q[c2].x, q[c2].y) : make_float2(q[c2].z, q[c2].w);
        float2 v1 = paired ? other : e[c2];
        float w0 = wyz * wx0, w1 = wyz * wx1;
        o0 = fmaf(w0, v0.x, o0); o1 = fmaf(w0, v0.y, o1);
        o0 = fmaf(w1, v1.x, o0); o1 = fmaf(w1, v1.y, o1);
    }

    float2 r;
    r.x = o0;
    r.y = o1;
    reinterpret_cast<float2*>(out)[(long)b * NUM_LEVELS + level] = r;
}

// ---------------------------------------------------------------------------
extern "C" void kernel_launch(void* const* d_in, const int* in_sizes, int n_in,
                              void* d_out, int out_size)
{
    const float*  inputs = (const float*)d_in[0];
    const float2* emb    = (const float2*)d_in[1];
    const float4* fs4    = (const float4*)d_in[2];
    const int*    sidx   = (const int*)d_in[3];
    const int*    boundp = (n_in > 4) ? (const int*)d_in[4] : nullptr;

    int B = in_sizes[0] / 3;
    int N = in_sizes[3];

    scatter_kernel<<<(N + 255) / 256, 256>>>(emb, sidx, N);
    blend_kernel<<<((TOTAL_PARAMS / 2) + 255) / 256, 256>>>(fs4);
    encode_kernel<<<(B * NUM_LEVELS + 255) / 256, 256>>>(inputs, boundp, (float*)d_out, B);
}